// round 14
// baseline (speedup 1.0000x reference)
#include <cuda_runtime.h>

#define BT 512
#define GRID 304   // 152 SMs x 2 CTAs, one persistent wave on GB300

typedef unsigned long long ull;

__device__ __forceinline__ ull pack2(float a, float b) {
    ull r;
    asm("mov.b64 %0, {%1, %2};" : "=l"(r) : "f"(a), "f"(b));
    return r;
}
__device__ __forceinline__ void unpack2(ull v, float& a, float& b) {
    asm("mov.b64 {%0, %1}, %2;" : "=f"(a), "=f"(b) : "l"(v));
}
__device__ __forceinline__ ull fma2(ull a, ull b, ull c) {
    ull d;
    asm("fma.rn.f32x2 %0, %1, %2, %3;" : "=l"(d) : "l"(a), "l"(b), "l"(c));
    return d;
}

__global__ __launch_bounds__(512, 2) void convintnet_kernel(
    const float* __restrict__ x,
    const float* __restrict__ bn_gamma, const float* __restrict__ bn_beta,
    const float* __restrict__ bn_mean, const float* __restrict__ bn_var,
    const float* __restrict__ eW1, const float* __restrict__ eb1,
    const float* __restrict__ eW2, const float* __restrict__ eb2,
    const float* __restrict__ eW3, const float* __restrict__ eb3,
    const float* __restrict__ dW1, const float* __restrict__ db1,
    const float* __restrict__ dW2, const float* __restrict__ db2,
    const float* __restrict__ dW3, const float* __restrict__ db3,
    const float* __restrict__ aW1, const float* __restrict__ ab1,
    const float* __restrict__ aW2, const float* __restrict__ ab2,
    float* __restrict__ out, int B)
{
    // ---- shared memory ----
    __shared__ __align__(16) float s_xn[800];     // [50][16]
    __shared__ __align__(16) float s_buf[3100];   // A=[50] stride 31; B at +1550; reused as d1=[50][45]
    __shared__ __align__(16) float s_eff[304];    // [50][6]
    __shared__ __align__(16) float s_d2[1100];    // [50][22]
    __shared__ __align__(16) float s_part[3008];  // edge partials [10][50][6]; reused as d3
    __shared__ __align__(16) float s_W1a[480], s_W1b[480], s_eb1[32];
    __shared__ __align__(16) float s_W2[512];     // [32][16] padded (col 15 = 0; rows 30,31 = 0)
    __shared__ __align__(16) float s_b2[16];      // b2[15]=0
    __shared__ __align__(16) float s_W3[128];     // [16][8] padded (row 15, cols 6,7 = 0)
    __shared__ __align__(16) float s_b3[8];
    __shared__ __align__(16) float s_dW1[992], s_db1[48];
    __shared__ __align__(16) float s_dW2[992], s_db2[24];
    __shared__ __align__(16) float s_dW3[132], s_db3[8];
    __shared__ __align__(16) float s_aW1[288], s_ab1[48];
    __shared__ __align__(16) float s_aW2[240], s_ab2[8];
    __shared__ __align__(16) float s_bns[16], s_bnt[16];
    __shared__ __align__(16) float s_dsum[8];
    __shared__ __align__(16) float s_a1[48];

    const int tid = threadIdx.x;

    // ---- params into smem (ONCE per persistent CTA) ----
    for (int i = tid; i < 480; i += BT) s_W1a[i] = eW1[i];
    for (int i = tid; i < 480; i += BT) s_W1b[i] = eW1[480 + i];
    for (int i = tid; i < 512; i += BT) {
        int r = i >> 4, c = i & 15;
        s_W2[i] = (r < 30 && c < 15) ? eW2[r * 15 + c] : 0.f;
    }
    for (int i = tid; i < 128; i += BT) {
        int r = i >> 3, c = i & 7;
        s_W3[i] = (r < 15 && c < 6) ? eW3[r * 6 + c] : 0.f;
    }
    for (int i = tid; i < 990; i += BT) s_dW1[i] = dW1[i];
    for (int i = tid; i < 990; i += BT) s_dW2[i] = dW2[i];
    for (int i = tid; i < 132; i += BT) s_dW3[i] = dW3[i];
    for (int i = tid; i < 288; i += BT) s_aW1[i] = aW1[i];
    for (int i = tid; i < 240; i += BT) s_aW2[i] = aW2[i];
    if (tid < 30) s_eb1[tid] = eb1[tid];
    if (tid < 45) s_db1[tid] = db1[tid];
    if (tid < 22) s_db2[tid] = db2[tid];
    if (tid < 6)  s_db3[tid] = db3[tid];
    if (tid < 48) s_ab1[tid] = ab1[tid];
    if (tid < 5)  s_ab2[tid] = ab2[tid];
    if (tid < 16) {
        s_b2[tid] = (tid < 15) ? eb2[tid] : 0.f;
        float sc = bn_gamma[tid] * rsqrtf(bn_var[tid] + 1e-3f);
        s_bns[tid] = sc;
        s_bnt[tid] = bn_beta[tid] - bn_mean[tid] * sc;
    }
    if (tid < 8) s_b3[tid] = (tid < 6) ? eb3[tid] : 0.f;
    __syncthreads();

    // ---- persistent loop over batch elements ----
    for (int b = blockIdx.x; b < B; b += GRID) {

        // ---- batchnorm ----
        const float* xb = x + b * 800;
        for (int i = tid; i < 800; i += BT) {
            int f = i & 15;
            s_xn[i] = fmaf(xb[i], s_bns[f], s_bnt[f]);
        }
        __syncthreads();

        // ---- factored edge layer 1: A[n]=xn[n]@W1_top+eb1, B[n]=xn[n]@W1_bot (row stride 31) ----
        for (int i = tid; i < 3000; i += BT) {
            int half = (i >= 1500);
            int idx  = half ? (i - 1500) : i;
            int n = idx / 30, k = idx - n * 30;
            const float* W = half ? s_W1b : s_W1a;
            float acc = half ? 0.f : s_eb1[k];
            const float* xr = s_xn + n * 16;
            #pragma unroll
            for (int f = 0; f < 16; f++) acc = fmaf(xr[f], W[f * 30 + k], acc);
            s_buf[(half ? 1550 : 0) + n * 31 + k] = acc;
        }
        __syncthreads();

        // ---- edge MLP: 10 threads/receiver; senders in PAIRS; layers 2 AND 3 packed f32x2 ----
        if (tid < 500) {
            const int r = tid / 10, sub = tid - r * 10;
            const float* Ar = s_buf + r * 31;

            float acc[6];
            #pragma unroll
            for (int m = 0; m < 6; m++) acc[m] = 0.f;

            int kk = sub;
            #pragma unroll 1
            for (; kk + 10 < 49; kk += 20) {
                const int kb = kk + 10;
                const int s1 = kk + (kk >= r);
                const int s2 = kb + (kb >= r);
                const float* B1 = s_buf + 1550 + s1 * 31;
                const float* B2 = s_buf + 1550 + s2 * 31;

                ull h2a[8], h2b[8];
                {
                    const ull* b2q = (const ull*)s_b2;
                    #pragma unroll
                    for (int p = 0; p < 8; p++) { ull v = b2q[p]; h2a[p] = v; h2b[p] = v; }
                }

                #pragma unroll 3
                for (int i = 0; i < 30; i++) {
                    float a0 = Ar[i];
                    float va = fmaxf(a0 + B1[i], 0.f);
                    float vb = fmaxf(a0 + B2[i], 0.f);
                    ull vva = pack2(va, va);
                    ull vvb = pack2(vb, vb);
                    const ulonglong2* w = (const ulonglong2*)(s_W2 + i * 16);
                    ulonglong2 wA = w[0], wB = w[1];
                    h2a[0] = fma2(vva, wA.x, h2a[0]); h2b[0] = fma2(vvb, wA.x, h2b[0]);
                    h2a[1] = fma2(vva, wA.y, h2a[1]); h2b[1] = fma2(vvb, wA.y, h2b[1]);
                    h2a[2] = fma2(vva, wB.x, h2a[2]); h2b[2] = fma2(vvb, wB.x, h2b[2]);
                    h2a[3] = fma2(vva, wB.y, h2a[3]); h2b[3] = fma2(vvb, wB.y, h2b[3]);
                    w = (const ulonglong2*)(s_W2 + i * 16 + 8);
                    wA = w[0]; wB = w[1];
                    h2a[4] = fma2(vva, wA.x, h2a[4]); h2b[4] = fma2(vvb, wA.x, h2b[4]);
                    h2a[5] = fma2(vva, wA.y, h2a[5]); h2b[5] = fma2(vvb, wA.y, h2b[5]);
                    h2a[6] = fma2(vva, wB.x, h2a[6]); h2b[6] = fma2(vvb, wB.x, h2b[6]);
                    h2a[7] = fma2(vva, wB.y, h2a[7]); h2b[7] = fma2(vvb, wB.y, h2b[7]);
                }

                ull h3a[3], h3b[3];
                {
                    const ull* b3q = (const ull*)s_b3;
                    #pragma unroll
                    for (int p = 0; p < 3; p++) { ull v = b3q[p]; h3a[p] = v; h3b[p] = v; }
                }

                #pragma unroll 4
                for (int p = 0; p < 8; p++) {
                    float a1, c1, a2, c2;
                    unpack2(h2a[p], a1, c1);
                    unpack2(h2b[p], a2, c2);
                    ull vva1 = pack2(fmaxf(a1, 0.f), fmaxf(a1, 0.f));
                    ull vva2 = pack2(fmaxf(a2, 0.f), fmaxf(a2, 0.f));
                    ull vvc1 = pack2(fmaxf(c1, 0.f), fmaxf(c1, 0.f));
                    ull vvc2 = pack2(fmaxf(c2, 0.f), fmaxf(c2, 0.f));
                    const ulonglong2* w = (const ulonglong2*)(s_W3 + (2 * p) * 8);
                    ulonglong2 wA = w[0], wB = w[1];
                    h3a[0] = fma2(vva1, wA.x, h3a[0]); h3b[0] = fma2(vva2, wA.x, h3b[0]);
                    h3a[1] = fma2(vva1, wA.y, h3a[1]); h3b[1] = fma2(vva2, wA.y, h3b[1]);
                    h3a[2] = fma2(vva1, wB.x, h3a[2]); h3b[2] = fma2(vva2, wB.x, h3b[2]);
                    w = (const ulonglong2*)(s_W3 + (2 * p + 1) * 8);
                    wA = w[0]; wB = w[1];
                    h3a[0] = fma2(vvc1, wA.x, h3a[0]); h3b[0] = fma2(vvc2, wA.x, h3b[0]);
                    h3a[1] = fma2(vvc1, wA.y, h3a[1]); h3b[1] = fma2(vvc2, wA.y, h3b[1]);
                    h3a[2] = fma2(vvc1, wB.x, h3a[2]); h3b[2] = fma2(vvc2, wB.x, h3b[2]);
                }

                #pragma unroll
                for (int p = 0; p < 3; p++) {
                    float x0, x1, y0, y1;
                    unpack2(h3a[p], x0, x1);
                    unpack2(h3b[p], y0, y1);
                    acc[2 * p]     += fmaxf(x0, 0.f) + fmaxf(y0, 0.f);
                    acc[2 * p + 1] += fmaxf(x1, 0.f) + fmaxf(y1, 0.f);
                }
            }

            // tail single edge
            if (kk < 49) {
                const int s = kk + (kk >= r);
                const float* Bs = s_buf + 1550 + s * 31;

                ull h2p[8];
                {
                    const ull* b2q = (const ull*)s_b2;
                    #pragma unroll
                    for (int p = 0; p < 8; p++) h2p[p] = b2q[p];
                }

                #pragma unroll 5
                for (int i = 0; i < 30; i++) {
                    float v = fmaxf(Ar[i] + Bs[i], 0.f);
                    ull vv = pack2(v, v);
                    const ulonglong2* w = (const ulonglong2*)(s_W2 + i * 16);
                    ulonglong2 wA = w[0], wB = w[1];
                    h2p[0] = fma2(vv, wA.x, h2p[0]);
                    h2p[1] = fma2(vv, wA.y, h2p[1]);
                    h2p[2] = fma2(vv, wB.x, h2p[2]);
                    h2p[3] = fma2(vv, wB.y, h2p[3]);
                    w = (const ulonglong2*)(s_W2 + i * 16 + 8);
                    wA = w[0]; wB = w[1];
                    h2p[4] = fma2(vv, wA.x, h2p[4]);
                    h2p[5] = fma2(vv, wA.y, h2p[5]);
                    h2p[6] = fma2(vv, wB.x, h2p[6]);
                    h2p[7] = fma2(vv, wB.y, h2p[7]);
                }

                ull h3p[3];
                {
                    const ull* b3q = (const ull*)s_b3;
                    #pragma unroll
                    for (int p = 0; p < 3; p++) h3p[p] = b3q[p];
                }

                #pragma unroll 4
                for (int p = 0; p < 8; p++) {
                    float a, c;
                    unpack2(h2p[p], a, c);
                    ull vva = pack2(fmaxf(a, 0.f), fmaxf(a, 0.f));
                    ull vvc = pack2(fmaxf(c, 0.f), fmaxf(c, 0.f));
                    const ulonglong2* w = (const ulonglong2*)(s_W3 + (2 * p) * 8);
                    ulonglong2 wA = w[0], wB = w[1];
                    h3p[0] = fma2(vva, wA.x, h3p[0]);
                    h3p[1] = fma2(vva, wA.y, h3p[1]);
                    h3p[2] = fma2(vva, wB.x, h3p[2]);
                    w = (const ulonglong2*)(s_W3 + (2 * p + 1) * 8);
                    wA = w[0]; wB = w[1];
                    h3p[0] = fma2(vvc, wA.x, h3p[0]);
                    h3p[1] = fma2(vvc, wA.y, h3p[1]);
                    h3p[2] = fma2(vvc, wB.x, h3p[2]);
                }

                #pragma unroll
                for (int p = 0; p < 3; p++) {
                    float x0, x1;
                    unpack2(h3p[p], x0, x1);
                    acc[2 * p]     += fmaxf(x0, 0.f);
                    acc[2 * p + 1] += fmaxf(x1, 0.f);
                }
            }

            float* dst = s_part + (sub * 50 + r) * 6;
            #pragma unroll
            for (int m = 0; m < 6; m++) dst[m] = acc[m];
        }
        __syncthreads();

        // ---- reduce partials: s_eff[r*6+m] = sum over 10 subs ----
        for (int i = tid; i < 300; i += BT) {
            float v = s_part[i];
            #pragma unroll
            for (int p = 1; p < 10; p++) v += s_part[p * 300 + i];
            s_eff[i] = v;
        }
        __syncthreads();

        // ---- dynamics layer 1: [xn | eff] (22) -> 45 (reuse s_buf as d1) ----
        for (int i = tid; i < 2250; i += BT) {
            int n = i / 45, o = i - n * 45;
            float acc = s_db1[o];
            const float* xr = s_xn + n * 16;
            #pragma unroll
            for (int f = 0; f < 16; f++) acc = fmaf(xr[f], s_dW1[f * 45 + o], acc);
            const float* er = s_eff + n * 6;
            #pragma unroll
            for (int m = 0; m < 6; m++) acc = fmaf(er[m], s_dW1[(16 + m) * 45 + o], acc);
            s_buf[i] = fmaxf(acc, 0.f);
        }
        __syncthreads();

        // ---- dynamics layer 2: 45 -> 22 ----
        for (int i = tid; i < 1100; i += BT) {
            int n = i / 22, o = i - n * 22;
            float acc = s_db2[o];
            const float* dr = s_buf + n * 45;
            #pragma unroll 9
            for (int j = 0; j < 45; j++) acc = fmaf(dr[j], s_dW2[j * 22 + o], acc);
            s_d2[i] = fmaxf(acc, 0.f);
        }
        __syncthreads();

        // ---- dynamics layer 3: 22 -> 6 per node, staged to smem ----
        for (int i = tid; i < 300; i += BT) {
            int n = i / 6, o = i - n * 6;
            float acc = s_db3[o];
            const float* dr = s_d2 + n * 22;
            #pragma unroll 11
            for (int j = 0; j < 22; j++) acc = fmaf(dr[j], s_dW3[j * 6 + o], acc);
            s_part[i] = fmaxf(acc, 0.f);
        }
        __syncthreads();

        // ---- sum over nodes: 6 threads x 50 ----
        if (tid < 6) {
            float v = 0.f;
            #pragma unroll 10
            for (int n = 0; n < 50; n++) v += s_part[n * 6 + tid];
            s_dsum[tid] = v;
        }
        __syncthreads();

        // ---- classifier layer 1: 6 -> 48 ----
        if (tid < 48) {
            float acc = s_ab1[tid];
            #pragma unroll
            for (int j = 0; j < 6; j++) acc = fmaf(s_dsum[j], s_aW1[j * 48 + tid], acc);
            s_a1[tid] = fmaxf(acc, 0.f);
        }
        __syncthreads();

        // ---- classifier layer 2 + softmax ----
        if (tid == 0) {
            float lg[5];
            #pragma unroll
            for (int o = 0; o < 5; o++) {
                float acc = s_ab2[o];
                #pragma unroll
                for (int j = 0; j < 48; j++) acc = fmaf(s_a1[j], s_aW2[j * 5 + o], acc);
                lg[o] = acc;
            }
            float mx = lg[0];
            #pragma unroll
            for (int o = 1; o < 5; o++) mx = fmaxf(mx, lg[o]);
            float e[5], sum = 0.f;
            #pragma unroll
            for (int o = 0; o < 5; o++) { e[o] = expf(lg[o] - mx); sum += e[o]; }
            float inv = 1.f / sum;
            #pragma unroll
            for (int o = 0; o < 5; o++) out[b * 5 + o] = e[o] * inv;
        }
        __syncthreads();   // protect s_xn/s_a1 before next batch overwrites
    }
}

extern "C" void kernel_launch(void* const* d_in, const int* in_sizes, int n_in,
                              void* d_out, int out_size) {
    const int B = in_sizes[0] / 800;  // x is [B, 50, 16]
    convintnet_kernel<<<GRID, BT>>>(
        (const float*)d_in[0],
        (const float*)d_in[1],  (const float*)d_in[2],
        (const float*)d_in[3],  (const float*)d_in[4],
        (const float*)d_in[5],  (const float*)d_in[6],
        (const float*)d_in[7],  (const float*)d_in[8],
        (const float*)d_in[9],  (const float*)d_in[10],
        (const float*)d_in[11], (const float*)d_in[12],
        (const float*)d_in[13], (const float*)d_in[14],
        (const float*)d_in[15], (const float*)d_in[16],
        (const float*)d_in[17], (const float*)d_in[18],
        (const float*)d_in[19], (const float*)d_in[20],
        (float*)d_out, B);
}

// round 15
// speedup vs baseline: 1.0200x; 1.0200x over previous
#include <cuda_runtime.h>

#define BT 512

typedef unsigned long long ull;

__device__ __forceinline__ ull pack2(float a, float b) {
    ull r;
    asm("mov.b64 %0, {%1, %2};" : "=l"(r) : "f"(a), "f"(b));
    return r;
}
__device__ __forceinline__ void unpack2(ull v, float& a, float& b) {
    asm("mov.b64 {%0, %1}, %2;" : "=f"(a), "=f"(b) : "l"(v));
}
__device__ __forceinline__ ull fma2(ull a, ull b, ull c) {
    ull d;
    asm("fma.rn.f32x2 %0, %1, %2, %3;" : "=l"(d) : "l"(a), "l"(b), "l"(c));
    return d;
}

// dual-edge layer-2 step at W2 row (va/vb pre-relu'd scalars)
#define EDGE2_ROW(va, vb, W2ROW)                                             \
    {                                                                        \
        ull vva = pack2(va, va);                                             \
        ull vvb = pack2(vb, vb);                                             \
        const ulonglong2* w = (const ulonglong2*)(W2ROW);                    \
        ulonglong2 wA = w[0], wB = w[1];                                     \
        h2a[0] = fma2(vva, wA.x, h2a[0]); h2b[0] = fma2(vvb, wA.x, h2b[0]);  \
        h2a[1] = fma2(vva, wA.y, h2a[1]); h2b[1] = fma2(vvb, wA.y, h2b[1]);  \
        h2a[2] = fma2(vva, wB.x, h2a[2]); h2b[2] = fma2(vvb, wB.x, h2b[2]);  \
        h2a[3] = fma2(vva, wB.y, h2a[3]); h2b[3] = fma2(vvb, wB.y, h2b[3]);  \
        w = (const ulonglong2*)((W2ROW) + 8);                                \
        wA = w[0]; wB = w[1];                                                \
        h2a[4] = fma2(vva, wA.x, h2a[4]); h2b[4] = fma2(vvb, wA.x, h2b[4]);  \
        h2a[5] = fma2(vva, wA.y, h2a[5]); h2b[5] = fma2(vvb, wA.y, h2b[5]);  \
        h2a[6] = fma2(vva, wB.x, h2a[6]); h2b[6] = fma2(vvb, wB.x, h2b[6]);  \
        h2a[7] = fma2(vva, wB.y, h2a[7]); h2b[7] = fma2(vvb, wB.y, h2b[7]);  \
    }

#define EDGE1_ROW(v, W2ROW)                                                  \
    {                                                                        \
        ull vv = pack2(v, v);                                                \
        const ulonglong2* w = (const ulonglong2*)(W2ROW);                    \
        ulonglong2 wA = w[0], wB = w[1];                                     \
        h2p[0] = fma2(vv, wA.x, h2p[0]);                                     \
        h2p[1] = fma2(vv, wA.y, h2p[1]);                                     \
        h2p[2] = fma2(vv, wB.x, h2p[2]);                                     \
        h2p[3] = fma2(vv, wB.y, h2p[3]);                                     \
        w = (const ulonglong2*)((W2ROW) + 8);                                \
        wA = w[0]; wB = w[1];                                                \
        h2p[4] = fma2(vv, wA.x, h2p[4]);                                     \
        h2p[5] = fma2(vv, wA.y, h2p[5]);                                     \
        h2p[6] = fma2(vv, wB.x, h2p[6]);                                     \
        h2p[7] = fma2(vv, wB.y, h2p[7]);                                     \
    }

__global__ __launch_bounds__(512, 2) void convintnet_kernel(
    const float* __restrict__ x,
    const float* __restrict__ bn_gamma, const float* __restrict__ bn_beta,
    const float* __restrict__ bn_mean, const float* __restrict__ bn_var,
    const float* __restrict__ eW1, const float* __restrict__ eb1,
    const float* __restrict__ eW2, const float* __restrict__ eb2,
    const float* __restrict__ eW3, const float* __restrict__ eb3,
    const float* __restrict__ dW1, const float* __restrict__ db1,
    const float* __restrict__ dW2, const float* __restrict__ db2,
    const float* __restrict__ dW3, const float* __restrict__ db3,
    const float* __restrict__ aW1, const float* __restrict__ ab1,
    const float* __restrict__ aW2, const float* __restrict__ ab2,
    float* __restrict__ out)
{
    // ---- shared memory ----
    __shared__ __align__(16) float s_xn[800];     // [50][16]
    __shared__ __align__(16) float s_buf[3400];   // A=[50] stride 34 at 0; B at +1700; reused as d1=[50][45]
    __shared__ __align__(16) float s_eff[304];    // [50][6]
    __shared__ __align__(16) float s_d2[1100];    // [50][22]
    __shared__ __align__(16) float s_part[3008];  // edge partials [10][50][6]; reused as d3
    __shared__ __align__(16) float s_W1a[480], s_W1b[480], s_eb1[32];
    __shared__ __align__(16) float s_W2[512];     // [32][16] padded (col 15 = 0; rows 30,31 = 0)
    __shared__ __align__(16) float s_b2[16];      // b2[15]=0
    __shared__ __align__(16) float s_W3[128];     // [16][8] padded (row 15, cols 6,7 = 0)
    __shared__ __align__(16) float s_b3[8];
    __shared__ __align__(16) float s_dW1[992], s_db1[48];
    __shared__ __align__(16) float s_dW2[992], s_db2[24];
    __shared__ __align__(16) float s_dW3[132], s_db3[8];
    __shared__ __align__(16) float s_aW1[288], s_ab1[48];
    __shared__ __align__(16) float s_aW2[240], s_ab2[8];
    __shared__ __align__(16) float s_bns[16], s_bnt[16];
    __shared__ __align__(16) float s_dsum[8];
    __shared__ __align__(16) float s_a1[48];

    const int tid = threadIdx.x;
    const int b   = blockIdx.x;

    // ---- params into smem ----
    for (int i = tid; i < 480; i += BT) s_W1a[i] = eW1[i];
    for (int i = tid; i < 480; i += BT) s_W1b[i] = eW1[480 + i];
    for (int i = tid; i < 512; i += BT) {
        int r = i >> 4, c = i & 15;
        s_W2[i] = (r < 30 && c < 15) ? eW2[r * 15 + c] : 0.f;
    }
    for (int i = tid; i < 128; i += BT) {
        int r = i >> 3, c = i & 7;
        s_W3[i] = (r < 15 && c < 6) ? eW3[r * 6 + c] : 0.f;
    }
    for (int i = tid; i < 990; i += BT) s_dW1[i] = dW1[i];
    for (int i = tid; i < 990; i += BT) s_dW2[i] = dW2[i];
    for (int i = tid; i < 132; i += BT) s_dW3[i] = dW3[i];
    for (int i = tid; i < 288; i += BT) s_aW1[i] = aW1[i];
    for (int i = tid; i < 240; i += BT) s_aW2[i] = aW2[i];
    if (tid < 30) s_eb1[tid] = eb1[tid];
    if (tid < 45) s_db1[tid] = db1[tid];
    if (tid < 22) s_db2[tid] = db2[tid];
    if (tid < 6)  s_db3[tid] = db3[tid];
    if (tid < 48) s_ab1[tid] = ab1[tid];
    if (tid < 5)  s_ab2[tid] = ab2[tid];
    if (tid < 16) {
        s_b2[tid] = (tid < 15) ? eb2[tid] : 0.f;
        float sc = bn_gamma[tid] * rsqrtf(bn_var[tid] + 1e-3f);
        s_bns[tid] = sc;
        s_bnt[tid] = bn_beta[tid] - bn_mean[tid] * sc;
    }
    if (tid < 8) s_b3[tid] = (tid < 6) ? eb3[tid] : 0.f;
    __syncthreads();

    // ---- batchnorm ----
    const float* xb = x + b * 800;
    for (int i = tid; i < 800; i += BT) {
        int f = i & 15;
        s_xn[i] = fmaf(xb[i], s_bns[f], s_bnt[f]);
    }
    __syncthreads();

    // ---- factored edge layer 1: A[n]=xn[n]@W1_top+eb1, B[n]=xn[n]@W1_bot (row stride 34) ----
    for (int i = tid; i < 3000; i += BT) {
        int half = (i >= 1500);
        int idx  = half ? (i - 1500) : i;
        int n = idx / 30, k = idx - n * 30;
        const float* W = half ? s_W1b : s_W1a;
        float acc = half ? 0.f : s_eb1[k];
        const float* xr = s_xn + n * 16;
        #pragma unroll
        for (int f = 0; f < 16; f++) acc = fmaf(xr[f], W[f * 30 + k], acc);
        s_buf[(half ? 1700 : 0) + n * 34 + k] = acc;
    }
    __syncthreads();

    // ---- edge MLP: 10 threads/receiver; sender PAIRS; A/B as float2 (stride 34 = 8B-aligned,
    //      conflict-free: s*17 mod 16 = s mod 16); layers 2+3 packed f32x2 ----
    if (tid < 500) {
        const int r = tid / 10, sub = tid - r * 10;
        const float2* Ar2 = (const float2*)(s_buf + r * 34);

        float acc[6];
        #pragma unroll
        for (int m = 0; m < 6; m++) acc[m] = 0.f;

        int kk = sub;
        #pragma unroll 1
        for (; kk + 10 < 49; kk += 20) {
            const int kb = kk + 10;
            const int s1 = kk + (kk >= r);
            const int s2 = kb + (kb >= r);
            const float2* B12 = (const float2*)(s_buf + 1700 + s1 * 34);
            const float2* B22 = (const float2*)(s_buf + 1700 + s2 * 34);

            ull h2a[8], h2b[8];
            {
                const ull* b2q = (const ull*)s_b2;
                #pragma unroll
                for (int p = 0; p < 8; p++) { ull v = b2q[p]; h2a[p] = v; h2b[p] = v; }
            }

            #pragma unroll 3
            for (int c = 0; c < 15; c++) {
                float2 a  = Ar2[c];
                float2 b1 = B12[c];
                float2 b2 = B22[c];
                float va = fmaxf(a.x + b1.x, 0.f);
                float vb = fmaxf(a.x + b2.x, 0.f);
                EDGE2_ROW(va, vb, s_W2 + (2 * c) * 16)
                va = fmaxf(a.y + b1.y, 0.f);
                vb = fmaxf(a.y + b2.y, 0.f);
                EDGE2_ROW(va, vb, s_W2 + (2 * c + 1) * 16)
            }

            ull h3a[3], h3b[3];
            {
                const ull* b3q = (const ull*)s_b3;
                #pragma unroll
                for (int p = 0; p < 3; p++) { ull v = b3q[p]; h3a[p] = v; h3b[p] = v; }
            }

            #pragma unroll 4
            for (int p = 0; p < 8; p++) {
                float a1, c1, a2, c2;
                unpack2(h2a[p], a1, c1);
                unpack2(h2b[p], a2, c2);
                ull vva1 = pack2(fmaxf(a1, 0.f), fmaxf(a1, 0.f));
                ull vva2 = pack2(fmaxf(a2, 0.f), fmaxf(a2, 0.f));
                ull vvc1 = pack2(fmaxf(c1, 0.f), fmaxf(c1, 0.f));
                ull vvc2 = pack2(fmaxf(c2, 0.f), fmaxf(c2, 0.f));
                const ulonglong2* w = (const ulonglong2*)(s_W3 + (2 * p) * 8);
                ulonglong2 wA = w[0], wB = w[1];
                h3a[0] = fma2(vva1, wA.x, h3a[0]); h3b[0] = fma2(vva2, wA.x, h3b[0]);
                h3a[1] = fma2(vva1, wA.y, h3a[1]); h3b[1] = fma2(vva2, wA.y, h3b[1]);
                h3a[2] = fma2(vva1, wB.x, h3a[2]); h3b[2] = fma2(vva2, wB.x, h3b[2]);
                w = (const ulonglong2*)(s_W3 + (2 * p + 1) * 8);
                wA = w[0]; wB = w[1];
                h3a[0] = fma2(vvc1, wA.x, h3a[0]); h3b[0] = fma2(vvc2, wA.x, h3b[0]);
                h3a[1] = fma2(vvc1, wA.y, h3a[1]); h3b[1] = fma2(vvc2, wA.y, h3b[1]);
                h3a[2] = fma2(vvc1, wB.x, h3a[2]); h3b[2] = fma2(vvc2, wB.x, h3b[2]);
            }

            #pragma unroll
            for (int p = 0; p < 3; p++) {
                float x0, x1, y0, y1;
                unpack2(h3a[p], x0, x1);
                unpack2(h3b[p], y0, y1);
                acc[2 * p]     += fmaxf(x0, 0.f) + fmaxf(y0, 0.f);
                acc[2 * p + 1] += fmaxf(x1, 0.f) + fmaxf(y1, 0.f);
            }
        }

        // tail single edge
        if (kk < 49) {
            const int s = kk + (kk >= r);
            const float2* Bs2 = (const float2*)(s_buf + 1700 + s * 34);

            ull h2p[8];
            {
                const ull* b2q = (const ull*)s_b2;
                #pragma unroll
                for (int p = 0; p < 8; p++) h2p[p] = b2q[p];
            }

            #pragma unroll 3
            for (int c = 0; c < 15; c++) {
                float2 a  = Ar2[c];
                float2 bx = Bs2[c];
                float v = fmaxf(a.x + bx.x, 0.f);
                EDGE1_ROW(v, s_W2 + (2 * c) * 16)
                v = fmaxf(a.y + bx.y, 0.f);
                EDGE1_ROW(v, s_W2 + (2 * c + 1) * 16)
            }

            ull h3p[3];
            {
                const ull* b3q = (const ull*)s_b3;
                #pragma unroll
                for (int p = 0; p < 3; p++) h3p[p] = b3q[p];
            }

            #pragma unroll 4
            for (int p = 0; p < 8; p++) {
                float a, c;
                unpack2(h2p[p], a, c);
                ull vva = pack2(fmaxf(a, 0.f), fmaxf(a, 0.f));
                ull vvc = pack2(fmaxf(c, 0.f), fmaxf(c, 0.f));
                const ulonglong2* w = (const ulonglong2*)(s_W3 + (2 * p) * 8);
                ulonglong2 wA = w[0], wB = w[1];
                h3p[0] = fma2(vva, wA.x, h3p[0]);
                h3p[1] = fma2(vva, wA.y, h3p[1]);
                h3p[2] = fma2(vva, wB.x, h3p[2]);
                w = (const ulonglong2*)(s_W3 + (2 * p + 1) * 8);
                wA = w[0]; wB = w[1];
                h3p[0] = fma2(vvc, wA.x, h3p[0]);
                h3p[1] = fma2(vvc, wA.y, h3p[1]);
                h3p[2] = fma2(vvc, wB.x, h3p[2]);
            }

            #pragma unroll
            for (int p = 0; p < 3; p++) {
                float x0, x1;
                unpack2(h3p[p], x0, x1);
                acc[2 * p]     += fmaxf(x0, 0.f);
                acc[2 * p + 1] += fmaxf(x1, 0.f);
            }
        }

        float* dst = s_part + (sub * 50 + r) * 6;
        #pragma unroll
        for (int m = 0; m < 6; m++) dst[m] = acc[m];
    }
    __syncthreads();

    // ---- reduce partials: s_eff[r*6+m] = sum over 10 subs ----
    for (int i = tid; i < 300; i += BT) {
        float v = s_part[i];
        #pragma unroll
        for (int p = 1; p < 10; p++) v += s_part[p * 300 + i];
        s_eff[i] = v;
    }
    __syncthreads();

    // ---- dynamics layer 1: [xn | eff] (22) -> 45 (reuse s_buf as d1) ----
    for (int i = tid; i < 2250; i += BT) {
        int n = i / 45, o = i - n * 45;
        float acc = s_db1[o];
        const float* xr = s_xn + n * 16;
        #pragma unroll
        for (int f = 0; f < 16; f++) acc = fmaf(xr[f], s_dW1[f * 45 + o], acc);
        const float* er = s_eff + n * 6;
        #pragma unroll
        for (int m = 0; m < 6; m++) acc = fmaf(er[m], s_dW1[(16 + m) * 45 + o], acc);
        s_buf[i] = fmaxf(acc, 0.f);
    }
    __syncthreads();

    // ---- dynamics layer 2: 45 -> 22 ----
    for (int i = tid; i < 1100; i += BT) {
        int n = i / 22, o = i - n * 22;
        float acc = s_db2[o];
        const float* dr = s_buf + n * 45;
        #pragma unroll 9
        for (int j = 0; j < 45; j++) acc = fmaf(dr[j], s_dW2[j * 22 + o], acc);
        s_d2[i] = fmaxf(acc, 0.f);
    }
    __syncthreads();

    // ---- dynamics layer 3: 22 -> 6 per node, staged to smem ----
    for (int i = tid; i < 300; i += BT) {
        int n = i / 6, o = i - n * 6;
        float acc = s_db3[o];
        const float* dr = s_d2 + n * 22;
        #pragma unroll 11
        for (int j = 0; j < 22; j++) acc = fmaf(dr[j], s_dW3[j * 6 + o], acc);
        s_part[i] = fmaxf(acc, 0.f);
    }
    __syncthreads();

    // ---- sum over nodes: 6 threads x 50 ----
    if (tid < 6) {
        float v = 0.f;
        #pragma unroll 10
        for (int n = 0; n < 50; n++) v += s_part[n * 6 + tid];
        s_dsum[tid] = v;
    }
    __syncthreads();

    // ---- classifier layer 1: 6 -> 48 ----
    if (tid < 48) {
        float acc = s_ab1[tid];
        #pragma unroll
        for (int j = 0; j < 6; j++) acc = fmaf(s_dsum[j], s_aW1[j * 48 + tid], acc);
        s_a1[tid] = fmaxf(acc, 0.f);
    }
    __syncthreads();

    // ---- classifier layer 2 + softmax ----
    if (tid == 0) {
        float lg[5];
        #pragma unroll
        for (int o = 0; o < 5; o++) {
            float acc = s_ab2[o];
            #pragma unroll
            for (int j = 0; j < 48; j++) acc = fmaf(s_a1[j], s_aW2[j * 5 + o], acc);
            lg[o] = acc;
        }
        float mx = lg[0];
        #pragma unroll
        for (int o = 1; o < 5; o++) mx = fmaxf(mx, lg[o]);
        float e[5], sum = 0.f;
        #pragma unroll
        for (int o = 0; o < 5; o++) { e[o] = expf(lg[o] - mx); sum += e[o]; }
        float inv = 1.f / sum;
        #pragma unroll
        for (int o = 0; o < 5; o++) out[b * 5 + o] = e[o] * inv;
    }
}

extern "C" void kernel_launch(void* const* d_in, const int* in_sizes, int n_in,
                              void* d_out, int out_size) {
    const int B = in_sizes[0] / 800;  // x is [B, 50, 16]
    convintnet_kernel<<<B, BT>>>(
        (const float*)d_in[0],
        (const float*)d_in[1],  (const float*)d_in[2],
        (const float*)d_in[3],  (const float*)d_in[4],
        (const float*)d_in[5],  (const float*)d_in[6],
        (const float*)d_in[7],  (const float*)d_in[8],
        (const float*)d_in[9],  (const float*)d_in[10],
        (const float*)d_in[11], (const float*)d_in[12],
        (const float*)d_in[13], (const float*)d_in[14],
        (const float*)d_in[15], (const float*)d_in[16],
        (const float*)d_in[17], (const float*)d_in[18],
        (const float*)d_in[19], (const float*)d_in[20],
        (float*)d_out);
}

// round 16
// speedup vs baseline: 1.0642x; 1.0433x over previous
#include <cuda_runtime.h>

#define BT 512

typedef unsigned long long ull;

__device__ __forceinline__ ull pack2(float a, float b) {
    ull r;
    asm("mov.b64 %0, {%1, %2};" : "=l"(r) : "f"(a), "f"(b));
    return r;
}
__device__ __forceinline__ void unpack2(ull v, float& a, float& b) {
    asm("mov.b64 {%0, %1}, %2;" : "=f"(a), "=f"(b) : "l"(v));
}
__device__ __forceinline__ ull fma2(ull a, ull b, ull c) {
    ull d;
    asm("fma.rn.f32x2 %0, %1, %2, %3;" : "=l"(d) : "l"(a), "l"(b), "l"(c));
    return d;
}

// dual-edge layer-2 step at W2 row (va/vb pre-relu'd scalars)
#define EDGE2_ROW(va, vb, W2ROW)                                             \
    {                                                                        \
        ull vva = pack2(va, va);                                             \
        ull vvb = pack2(vb, vb);                                             \
        const ulonglong2* w = (const ulonglong2*)(W2ROW);                    \
        ulonglong2 wA = w[0], wB = w[1];                                     \
        h2a[0] = fma2(vva, wA.x, h2a[0]); h2b[0] = fma2(vvb, wA.x, h2b[0]);  \
        h2a[1] = fma2(vva, wA.y, h2a[1]); h2b[1] = fma2(vvb, wA.y, h2b[1]);  \
        h2a[2] = fma2(vva, wB.x, h2a[2]); h2b[2] = fma2(vvb, wB.x, h2b[2]);  \
        h2a[3] = fma2(vva, wB.y, h2a[3]); h2b[3] = fma2(vvb, wB.y, h2b[3]);  \
        w = (const ulonglong2*)((W2ROW) + 8);                                \
        wA = w[0]; wB = w[1];                                                \
        h2a[4] = fma2(vva, wA.x, h2a[4]); h2b[4] = fma2(vvb, wA.x, h2b[4]);  \
        h2a[5] = fma2(vva, wA.y, h2a[5]); h2b[5] = fma2(vvb, wA.y, h2b[5]);  \
        h2a[6] = fma2(vva, wB.x, h2a[6]); h2b[6] = fma2(vvb, wB.x, h2b[6]);  \
        h2a[7] = fma2(vva, wB.y, h2a[7]); h2b[7] = fma2(vvb, wB.y, h2b[7]);  \
    }

#define EDGE1_ROW(v, W2ROW)                                                  \
    {                                                                        \
        ull vv = pack2(v, v);                                                \
        const ulonglong2* w = (const ulonglong2*)(W2ROW);                    \
        ulonglong2 wA = w[0], wB = w[1];                                     \
        h2p[0] = fma2(vv, wA.x, h2p[0]);                                     \
        h2p[1] = fma2(vv, wA.y, h2p[1]);                                     \
        h2p[2] = fma2(vv, wB.x, h2p[2]);                                     \
        h2p[3] = fma2(vv, wB.y, h2p[3]);                                     \
        w = (const ulonglong2*)((W2ROW) + 8);                                \
        wA = w[0]; wB = w[1];                                                \
        h2p[4] = fma2(vv, wA.x, h2p[4]);                                     \
        h2p[5] = fma2(vv, wA.y, h2p[5]);                                     \
        h2p[6] = fma2(vv, wB.x, h2p[6]);                                     \
        h2p[7] = fma2(vv, wB.y, h2p[7]);                                     \
    }

__global__ __launch_bounds__(512, 2) void convintnet_kernel(
    const float* __restrict__ x,
    const float* __restrict__ bn_gamma, const float* __restrict__ bn_beta,
    const float* __restrict__ bn_mean, const float* __restrict__ bn_var,
    const float* __restrict__ eW1, const float* __restrict__ eb1,
    const float* __restrict__ eW2, const float* __restrict__ eb2,
    const float* __restrict__ eW3, const float* __restrict__ eb3,
    const float* __restrict__ dW1, const float* __restrict__ db1,
    const float* __restrict__ dW2, const float* __restrict__ db2,
    const float* __restrict__ dW3, const float* __restrict__ db3,
    const float* __restrict__ aW1, const float* __restrict__ ab1,
    const float* __restrict__ aW2, const float* __restrict__ ab2,
    float* __restrict__ out)
{
    // ---- shared memory ----
    __shared__ __align__(16) float s_xn[800];     // [50][16]
    __shared__ __align__(16) float s_buf[3400];   // At=[30][52] at 0; Bt=[30][52] at 1560; reused as d1=[50][45]
    __shared__ __align__(16) float s_eff[304];    // [50][6]
    __shared__ __align__(16) float s_d2[1100];    // [50][22]
    __shared__ __align__(16) float s_part[3008];  // edge partials [10][50][6]; reused as d3
    __shared__ __align__(16) float s_W1a[480], s_W1b[480], s_eb1[32];
    __shared__ __align__(16) float s_W2[512];     // [32][16] padded (col 15 = 0; rows 30,31 = 0)
    __shared__ __align__(16) float s_b2[16];      // b2[15]=0
    __shared__ __align__(16) float s_W3[128];     // [16][8] padded (row 15, cols 6,7 = 0)
    __shared__ __align__(16) float s_b3[8];
    __shared__ __align__(16) float s_dW1[992], s_db1[48];
    __shared__ __align__(16) float s_dW2[992], s_db2[24];
    __shared__ __align__(16) float s_dW3[132], s_db3[8];
    __shared__ __align__(16) float s_aW1[288], s_ab1[48];
    __shared__ __align__(16) float s_aW2[240], s_ab2[8];
    __shared__ __align__(16) float s_bns[16], s_bnt[16];
    __shared__ __align__(16) float s_dsum[8];
    __shared__ __align__(16) float s_a1[48];

    const int tid = threadIdx.x;
    const int b   = blockIdx.x;

    // ---- params into smem ----
    for (int i = tid; i < 480; i += BT) s_W1a[i] = eW1[i];
    for (int i = tid; i < 480; i += BT) s_W1b[i] = eW1[480 + i];
    for (int i = tid; i < 512; i += BT) {
        int r = i >> 4, c = i & 15;
        s_W2[i] = (r < 30 && c < 15) ? eW2[r * 15 + c] : 0.f;
    }
    for (int i = tid; i < 128; i += BT) {
        int r = i >> 3, c = i & 7;
        s_W3[i] = (r < 15 && c < 6) ? eW3[r * 6 + c] : 0.f;
    }
    for (int i = tid; i < 990; i += BT) s_dW1[i] = dW1[i];
    for (int i = tid; i < 990; i += BT) s_dW2[i] = dW2[i];
    for (int i = tid; i < 132; i += BT) s_dW3[i] = dW3[i];
    for (int i = tid; i < 288; i += BT) s_aW1[i] = aW1[i];
    for (int i = tid; i < 240; i += BT) s_aW2[i] = aW2[i];
    if (tid < 30) s_eb1[tid] = eb1[tid];
    if (tid < 45) s_db1[tid] = db1[tid];
    if (tid < 22) s_db2[tid] = db2[tid];
    if (tid < 6)  s_db3[tid] = db3[tid];
    if (tid < 48) s_ab1[tid] = ab1[tid];
    if (tid < 5)  s_ab2[tid] = ab2[tid];
    if (tid < 16) {
        s_b2[tid] = (tid < 15) ? eb2[tid] : 0.f;
        float sc = bn_gamma[tid] * rsqrtf(bn_var[tid] + 1e-3f);
        s_bns[tid] = sc;
        s_bnt[tid] = bn_beta[tid] - bn_mean[tid] * sc;
    }
    if (tid < 8) s_b3[tid] = (tid < 6) ? eb3[tid] : 0.f;
    __syncthreads();

    // ---- batchnorm ----
    const float* xb = x + b * 800;
    for (int i = tid; i < 800; i += BT) {
        int f = i & 15;
        s_xn[i] = fmaf(xb[i], s_bns[f], s_bnt[f]);
    }
    __syncthreads();

    // ---- factored edge layer 1, TRANSPOSED outputs: At[k][n], Bt[k][n] (stride 52) ----
    for (int i = tid; i < 3000; i += BT) {
        int half = (i >= 1500);
        int idx  = half ? (i - 1500) : i;
        int n = idx / 30, k = idx - n * 30;
        const float* W = half ? s_W1b : s_W1a;
        float acc = half ? 0.f : s_eb1[k];
        const float* xr = s_xn + n * 16;
        #pragma unroll
        for (int f = 0; f < 16; f++) acc = fmaf(xr[f], W[f * 30 + k], acc);
        s_buf[(half ? 1560 : 0) + k * 52 + n] = acc;
    }
    __syncthreads();

    // ---- edge MLP, receiver-major lanes: r = tid%50 (consecutive in warp), sub = tid/50.
    //      All 50 senders in uniform pairs (2j,2j+1); self-edge included, subtracted after.
    //      At reads coalesced, Bt reads warp-uniform broadcast float2. ----
    if (tid < 500) {
        const int r = tid % 50, sub = tid / 50;
        const int npairs = (sub < 5) ? 3 : 2;

        float acc[6];
        #pragma unroll
        for (int m = 0; m < 6; m++) acc[m] = 0.f;

        #pragma unroll 1
        for (int t = 0; t < npairs; t++) {
            const int j = sub + 10 * t;
            const float* Bp = s_buf + 1560 + 2 * j;    // Bt[i][2j..2j+1], row stride 52

            ull h2a[8], h2b[8];
            {
                const ull* b2q = (const ull*)s_b2;
                #pragma unroll
                for (int p = 0; p < 8; p++) { ull v = b2q[p]; h2a[p] = v; h2b[p] = v; }
            }

            #pragma unroll 3
            for (int i = 0; i < 30; i++) {
                float a0 = s_buf[i * 52 + r];               // coalesced per-lane
                float2 bb = *(const float2*)(Bp + i * 52);  // warp-uniform broadcast
                float va = fmaxf(a0 + bb.x, 0.f);
                float vb = fmaxf(a0 + bb.y, 0.f);
                EDGE2_ROW(va, vb, s_W2 + i * 16)
            }

            ull h3a[3], h3b[3];
            {
                const ull* b3q = (const ull*)s_b3;
                #pragma unroll
                for (int p = 0; p < 3; p++) { ull v = b3q[p]; h3a[p] = v; h3b[p] = v; }
            }

            #pragma unroll 4
            for (int p = 0; p < 8; p++) {
                float a1, c1, a2, c2;
                unpack2(h2a[p], a1, c1);
                unpack2(h2b[p], a2, c2);
                ull vva1 = pack2(fmaxf(a1, 0.f), fmaxf(a1, 0.f));
                ull vva2 = pack2(fmaxf(a2, 0.f), fmaxf(a2, 0.f));
                ull vvc1 = pack2(fmaxf(c1, 0.f), fmaxf(c1, 0.f));
                ull vvc2 = pack2(fmaxf(c2, 0.f), fmaxf(c2, 0.f));
                const ulonglong2* w = (const ulonglong2*)(s_W3 + (2 * p) * 8);
                ulonglong2 wA = w[0], wB = w[1];
                h3a[0] = fma2(vva1, wA.x, h3a[0]); h3b[0] = fma2(vva2, wA.x, h3b[0]);
                h3a[1] = fma2(vva1, wA.y, h3a[1]); h3b[1] = fma2(vva2, wA.y, h3b[1]);
                h3a[2] = fma2(vva1, wB.x, h3a[2]); h3b[2] = fma2(vva2, wB.x, h3b[2]);
                w = (const ulonglong2*)(s_W3 + (2 * p + 1) * 8);
                wA = w[0]; wB = w[1];
                h3a[0] = fma2(vvc1, wA.x, h3a[0]); h3b[0] = fma2(vvc2, wA.x, h3b[0]);
                h3a[1] = fma2(vvc1, wA.y, h3a[1]); h3b[1] = fma2(vvc2, wA.y, h3b[1]);
                h3a[2] = fma2(vvc1, wB.x, h3a[2]); h3b[2] = fma2(vvc2, wB.x, h3b[2]);
            }

            #pragma unroll
            for (int p = 0; p < 3; p++) {
                float x0, x1, y0, y1;
                unpack2(h3a[p], x0, x1);
                unpack2(h3b[p], y0, y1);
                acc[2 * p]     += fmaxf(x0, 0.f) + fmaxf(y0, 0.f);
                acc[2 * p + 1] += fmaxf(x1, 0.f) + fmaxf(y1, 0.f);
            }
        }

        float* dst = s_part + tid * 6;   // == (sub*50 + r)*6
        #pragma unroll
        for (int m = 0; m < 6; m++) dst[m] = acc[m];
    }
    __syncthreads();

    // ---- reduce partials: s_eff[r*6+m] = sum over 10 subs ----
    for (int i = tid; i < 300; i += BT) {
        float v = s_part[i];
        #pragma unroll
        for (int p = 1; p < 10; p++) v += s_part[p * 300 + i];
        s_eff[i] = v;
    }
    __syncthreads();

    // ---- subtract the self-edge (r,r) included in the full 50-sender sum ----
    if (tid < 50) {
        const int r = tid;

        ull h2p[8];
        {
            const ull* b2q = (const ull*)s_b2;
            #pragma unroll
            for (int p = 0; p < 8; p++) h2p[p] = b2q[p];
        }

        #pragma unroll 5
        for (int i = 0; i < 30; i++) {
            float v = fmaxf(s_buf[i * 52 + r] + s_buf[1560 + i * 52 + r], 0.f);
            EDGE1_ROW(v, s_W2 + i * 16)
        }

        ull h3p[3];
        {
            const ull* b3q = (const ull*)s_b3;
            #pragma unroll
            for (int p = 0; p < 3; p++) h3p[p] = b3q[p];
        }

        #pragma unroll 4
        for (int p = 0; p < 8; p++) {
            float a, c;
            unpack2(h2p[p], a, c);
            ull vva = pack2(fmaxf(a, 0.f), fmaxf(a, 0.f));
            ull vvc = pack2(fmaxf(c, 0.f), fmaxf(c, 0.f));
            const ulonglong2* w = (const ulonglong2*)(s_W3 + (2 * p) * 8);
            ulonglong2 wA = w[0], wB = w[1];
            h3p[0] = fma2(vva, wA.x, h3p[0]);
            h3p[1] = fma2(vva, wA.y, h3p[1]);
            h3p[2] = fma2(vva, wB.x, h3p[2]);
            w = (const ulonglong2*)(s_W3 + (2 * p + 1) * 8);
            wA = w[0]; wB = w[1];
            h3p[0] = fma2(vvc, wA.x, h3p[0]);
            h3p[1] = fma2(vvc, wA.y, h3p[1]);
            h3p[2] = fma2(vvc, wB.x, h3p[2]);
        }

        #pragma unroll
        for (int p = 0; p < 3; p++) {
            float x0, x1;
            unpack2(h3p[p], x0, x1);
            s_eff[r * 6 + 2 * p]     -= fmaxf(x0, 0.f);
            s_eff[r * 6 + 2 * p + 1] -= fmaxf(x1, 0.f);
        }
    }
    __syncthreads();

    // ---- dynamics layer 1: [xn | eff] (22) -> 45 (reuse s_buf as d1) ----
    for (int i = tid; i < 2250; i += BT) {
        int n = i / 45, o = i - n * 45;
        float acc = s_db1[o];
        const float* xr = s_xn + n * 16;
        #pragma unroll
        for (int f = 0; f < 16; f++) acc = fmaf(xr[f], s_dW1[f * 45 + o], acc);
        const float* er = s_eff + n * 6;
        #pragma unroll
        for (int m = 0; m < 6; m++) acc = fmaf(er[m], s_dW1[(16 + m) * 45 + o], acc);
        s_buf[i] = fmaxf(acc, 0.f);
    }
    __syncthreads();

    // ---- dynamics layer 2: 45 -> 22 ----
    for (int i = tid; i < 1100; i += BT) {
        int n = i / 22, o = i - n * 22;
        float acc = s_db2[o];
        const float* dr = s_buf + n * 45;
        #pragma unroll 9
        for (int j = 0; j < 45; j++) acc = fmaf(dr[j], s_dW2[j * 22 + o], acc);
        s_d2[i] = fmaxf(acc, 0.f);
    }
    __syncthreads();

    // ---- dynamics layer 3: 22 -> 6 per node, staged to smem ----
    for (int i = tid; i < 300; i += BT) {
        int n = i / 6, o = i - n * 6;
        float acc = s_db3[o];
        const float* dr = s_d2 + n * 22;
        #pragma unroll 11
        for (int j = 0; j < 22; j++) acc = fmaf(dr[j], s_dW3[j * 6 + o], acc);
        s_part[i] = fmaxf(acc, 0.f);
    }
    __syncthreads();

    // ---- sum over nodes: 6 threads x 50 ----
    if (tid < 6) {
        float v = 0.f;
        #pragma unroll 10
        for (int n = 0; n < 50; n++) v += s_part[n * 6 + tid];
        s_dsum[tid] = v;
    }
    __syncthreads();

    // ---- classifier layer 1: 6 -> 48 ----
    if (tid < 48) {
        float acc = s_ab1[tid];
        #pragma unroll
        for (int j = 0; j < 6; j++) acc = fmaf(s_dsum[j], s_aW1[j * 48 + tid], acc);
        s_a1[tid] = fmaxf(acc, 0.f);
    }
    __syncthreads();

    // ---- classifier layer 2 + softmax ----
    if (tid == 0) {
        float lg[5];
        #pragma unroll
        for (int o = 0; o < 5; o++) {
            float acc = s_ab2[o];
            #pragma unroll
            for (int j = 0; j < 48; j++) acc = fmaf(s_a1[j], s_aW2[j * 5 + o], acc);
            lg[o] = acc;
        }
        float mx = lg[0];
        #pragma unroll
        for (int o = 1; o < 5; o++) mx = fmaxf(mx, lg[o]);
        float e[5], sum = 0.f;
        #pragma unroll
        for (int o = 0; o < 5; o++) { e[o] = expf(lg[o] - mx); sum += e[o]; }
        float inv = 1.f / sum;
        #pragma unroll
        for (int o = 0; o < 5; o++) out[b * 5 + o] = e[o] * inv;
    }
}

extern "C" void kernel_launch(void* const* d_in, const int* in_sizes, int n_in,
                              void* d_out, int out_size) {
    const int B = in_sizes[0] / 800;  // x is [B, 50, 16]
    convintnet_kernel<<<B, BT>>>(
        (const float*)d_in[0],
        (const float*)d_in[1],  (const float*)d_in[2],
        (const float*)d_in[3],  (const float*)d_in[4],
        (const float*)d_in[5],  (const float*)d_in[6],
        (const float*)d_in[7],  (const float*)d_in[8],
        (const float*)d_in[9],  (const float*)d_in[10],
        (const float*)d_in[11], (const float*)d_in[12],
        (const float*)d_in[13], (const float*)d_in[14],
        (const float*)d_in[15], (const float*)d_in[16],
        (const float*)d_in[17], (const float*)d_in[18],
        (const float*)d_in[19], (const float*)d_in[20],
        (float*)d_out);
}